// round 9
// baseline (speedup 1.0000x reference)
#include <cuda_runtime.h>
#include <cuda_bf16.h>
#include <math.h>
#include <stdint.h>

// ---------------------------------------------------------------------------
// Problem constants
// ---------------------------------------------------------------------------
#define NNODES 10000
#define NIN    2000
#define D1     500
#define D2     500
#define D3     2000
#define NZC    64
#define COMS_D 3064
#define EMAX   131072

// ---------------------------------------------------------------------------
// Scratch (device globals; no allocations allowed)
// ---------------------------------------------------------------------------
__device__ float g_zbuf [NNODES * NZC];
__device__ float g_gbuf [NNODES * 2000];
__device__ float g_traw [NNODES * 2000];
__device__ float g_t1[NNODES * 500];
__device__ float g_t2[NNODES * 500];
__device__ float g_t3[NNODES * 2000];
__device__ float g_t4[NNODES * NZC];
__device__ float g_u [NNODES * 5];
__device__ float g_ztopo[NNODES * NZC];
__device__ float g_scores[NNODES * 2];
__device__ float g_embp[NNODES * NZC];
__device__ float g_mean[4096];
__device__ float g_rstd[4096];

// CSR build
__device__ int   g_cnt[NNODES + 1];
__device__ int   g_rowptr[NNODES + 1];
__device__ int   g_wp[NNODES];
__device__ int   g_scol[EMAX];
__device__ float g_sval[EMAX];

// bf16 split-precision ping-pong A buffers + weight buffers
__device__ __align__(256) __nv_bfloat16 g_A0hi[(size_t)NNODES * 3072];
__device__ __align__(256) __nv_bfloat16 g_A0lo[(size_t)NNODES * 3072];
__device__ __align__(256) __nv_bfloat16 g_A1hi[(size_t)NNODES * 3072];
__device__ __align__(256) __nv_bfloat16 g_A1lo[(size_t)NNODES * 3072];
__device__ __align__(256) __nv_bfloat16 g_Whi[2048 * 3072];
__device__ __align__(256) __nv_bfloat16 g_Wlo[2048 * 3072];

// ---------------------------------------------------------------------------
// PTX helpers
// ---------------------------------------------------------------------------
__device__ __forceinline__ void ldsm4(uint32_t* r, uint32_t addr) {
    asm volatile("ldmatrix.sync.aligned.m8n8.x4.shared.b16 {%0,%1,%2,%3}, [%4];"
                 : "=r"(r[0]), "=r"(r[1]), "=r"(r[2]), "=r"(r[3]) : "r"(addr));
}
__device__ __forceinline__ uint32_t smem_u32(const void* p) {
    uint32_t a;
    asm("{ .reg .u64 t; cvta.to.shared.u64 t, %1; cvt.u32.u64 %0, t; }" : "=r"(a) : "l"(p));
    return a;
}
__device__ __forceinline__ void mma16816(float* c, const uint32_t* a, const uint32_t* b) {
    asm volatile(
        "mma.sync.aligned.m16n8k16.row.col.f32.bf16.bf16.f32 "
        "{%0,%1,%2,%3}, {%4,%5,%6,%7}, {%8,%9}, {%0,%1,%2,%3};"
        : "+f"(c[0]), "+f"(c[1]), "+f"(c[2]), "+f"(c[3])
        : "r"(a[0]), "r"(a[1]), "r"(a[2]), "r"(a[3]), "r"(b[0]), "r"(b[1]));
}
__device__ __forceinline__ void split_bf16(float v, __nv_bfloat16& h, __nv_bfloat16& l) {
    h = __float2bfloat16(v);
    l = __float2bfloat16(v - __bfloat162float(h));
}
__device__ __forceinline__ void cpa16(uint32_t dst, const void* src) {
    asm volatile("cp.async.cg.shared.global [%0], [%1], 16;" :: "r"(dst), "l"(src));
}
__device__ __forceinline__ void cp_commit() {
    asm volatile("cp.async.commit_group;" ::: "memory");
}
template<int N>
__device__ __forceinline__ void cp_wait() {
    asm volatile("cp.async.wait_group %0;" :: "n"(N) : "memory");
}

// ---------------------------------------------------------------------------
// Split-bf16 mma.sync GEMM: BM=128, BN=128, BK=32, 128 threads, 4 warps,
// warp tile 64x64, cp.async 2-stage pipeline.
// C may be nullptr. mode: 0 none, 1 +bias, 2 +bias+elu
// ---------------------------------------------------------------------------
#define ROWB 80
#define TILE_BYTES (128 * ROWB)        // 10240 each for Ahi/Alo/Bhi/Blo
#define STAGE_BYTES (4 * TILE_BYTES)   // 40960
#define GEMM_DSMEM (2 * STAGE_BYTES)   // 81920

__device__ __forceinline__ void load_stage_async(
    uint32_t sbase,
    const __nv_bfloat16* __restrict__ Ahi, const __nv_bfloat16* __restrict__ Alo,
    const __nv_bfloat16* __restrict__ Bhi, const __nv_bfloat16* __restrict__ Blo,
    int mBase, int M, int nBase, int N, int Kpad, int k0, int tid)
{
#pragma unroll
    for (int it = 0; it < 4; it++) {
        int t = tid + it * 128;
        int row = t >> 2, seg = t & 3;
        uint32_t d = sbase + row * ROWB + seg * 16;
        int gr = mBase + row;
        int sr = (gr < M) ? gr : 0;
        size_t aoff = (size_t)sr * Kpad + k0 + seg * 8;
        cpa16(d,              Ahi + aoff);
        cpa16(d + TILE_BYTES, Alo + aoff);
        int gn = nBase + row;
        int sn = (gn < N) ? gn : 0;
        size_t boff = (size_t)sn * Kpad + k0 + seg * 8;
        cpa16(d + 2 * TILE_BYTES, Bhi + boff);
        cpa16(d + 3 * TILE_BYTES, Blo + boff);
    }
}

__global__ __launch_bounds__(128, 2) void mma_gemm_kernel(
    const __nv_bfloat16* __restrict__ Ahi, const __nv_bfloat16* __restrict__ Alo,
    const __nv_bfloat16* __restrict__ Bhi, const __nv_bfloat16* __restrict__ Blo,
    const float* __restrict__ bias, float* __restrict__ C,
    __nv_bfloat16* __restrict__ outHi, __nv_bfloat16* __restrict__ outLo, int KpadOut,
    int M, int Ncol, int Kpad, int mode)
{
    extern __shared__ __align__(256) char smem[];
    uint32_t sb = smem_u32(smem);
    int tid = threadIdx.x;
    int wid = tid >> 5, lane = tid & 31;
    int wm = wid & 1;          // m-warp 0..1 (64 rows each)
    int wn = wid >> 1;         // n-warp 0..1 (64 cols each)
    int mBase = blockIdx.y * 128;
    int nBase = blockIdx.x * 128;

    float acc[4][8][4];
#pragma unroll
    for (int mt = 0; mt < 4; mt++)
#pragma unroll
        for (int nt = 0; nt < 8; nt++)
#pragma unroll
            for (int r = 0; r < 4; r++) acc[mt][nt][r] = 0.f;

    const int nc = Kpad >> 5;

    // prologue: fill both stages
    load_stage_async(sb, Ahi, Alo, Bhi, Blo, mBase, M, nBase, Ncol, Kpad, 0, tid);
    cp_commit();
    if (nc > 1) {
        load_stage_async(sb + STAGE_BYTES, Ahi, Alo, Bhi, Blo, mBase, M, nBase, Ncol, Kpad, 32, tid);
        cp_commit();
    }

    int lrow = (lane & 7) + ((lane >> 3) & 1) * 8;
    int lcol8 = (lane >> 4) * 8;

    for (int c = 0; c < nc; c++) {
        if (c + 1 < nc) cp_wait<1>(); else cp_wait<0>();
        __syncthreads();

        uint32_t bufU = sb + (c & 1) * STAGE_BYTES;
        uint32_t aHiS = bufU;
        uint32_t aLoS = bufU + TILE_BYTES;
        uint32_t bHiS = bufU + 2 * TILE_BYTES;
        uint32_t bLoS = bufU + 3 * TILE_BYTES;

#pragma unroll
        for (int ks = 0; ks < 2; ks++) {
            int kc = ks * 16 + lcol8;
            uint32_t ah[4][4], bb[8][2], xo[4][4];
            // load A-hi (64 rows), B-hi (64 cols)
#pragma unroll
            for (int mt = 0; mt < 4; mt++)
                ldsm4(ah[mt], aHiS + (wm * 64 + mt * 16 + lrow) * ROWB + kc * 2);
#pragma unroll
            for (int ntp = 0; ntp < 4; ntp++) {
                uint32_t t[4];
                ldsm4(t, bHiS + (wn * 64 + ntp * 16 + lrow) * ROWB + kc * 2);
                bb[2 * ntp][0] = t[0]; bb[2 * ntp][1] = t[2];
                bb[2 * ntp + 1][0] = t[1]; bb[2 * ntp + 1][1] = t[3];
            }
            // pass 1: hi*hi
#pragma unroll
            for (int mt = 0; mt < 4; mt++)
#pragma unroll
                for (int nt = 0; nt < 8; nt++)
                    mma16816(acc[mt][nt], ah[mt], bb[nt]);
            // load A-lo; pass 2: lo*hi (B-hi still live)
#pragma unroll
            for (int mt = 0; mt < 4; mt++)
                ldsm4(xo[mt], aLoS + (wm * 64 + mt * 16 + lrow) * ROWB + kc * 2);
#pragma unroll
            for (int mt = 0; mt < 4; mt++)
#pragma unroll
                for (int nt = 0; nt < 8; nt++)
                    mma16816(acc[mt][nt], xo[mt], bb[nt]);
            // load B-lo (overwrite bb); pass 3: hi*lo
#pragma unroll
            for (int ntp = 0; ntp < 4; ntp++) {
                uint32_t t[4];
                ldsm4(t, bLoS + (wn * 64 + ntp * 16 + lrow) * ROWB + kc * 2);
                bb[2 * ntp][0] = t[0]; bb[2 * ntp][1] = t[2];
                bb[2 * ntp + 1][0] = t[1]; bb[2 * ntp + 1][1] = t[3];
            }
#pragma unroll
            for (int mt = 0; mt < 4; mt++)
#pragma unroll
                for (int nt = 0; nt < 8; nt++)
                    mma16816(acc[mt][nt], ah[mt], bb[nt]);
        }
        __syncthreads();
        if (c + 2 < nc) {
            load_stage_async(sb + (c & 1) * STAGE_BYTES, Ahi, Alo, Bhi, Blo,
                             mBase, M, nBase, Ncol, Kpad, (c + 2) * 32, tid);
            cp_commit();
        }
    }

    // Epilogue
    int qr = lane >> 2;
    int qc = (lane & 3) * 2;
#pragma unroll
    for (int mt = 0; mt < 4; mt++) {
#pragma unroll
        for (int nt = 0; nt < 8; nt++) {
#pragma unroll
            for (int half = 0; half < 2; half++) {
                int gr = mBase + wm * 64 + mt * 16 + qr + half * 8;
                if (gr >= M) continue;
#pragma unroll
                for (int e = 0; e < 2; e++) {
                    int gc = nBase + wn * 64 + nt * 8 + qc + e;
                    float v = acc[mt][nt][half * 2 + e];
                    if (gc < Ncol) {
                        if (mode >= 1) v += bias[gc];
                        if (mode == 2) v = v > 0.f ? v : expm1f(v);
                        if (C) C[(size_t)gr * Ncol + gc] = v;
                    } else {
                        v = 0.f;
                    }
                    if (outHi && gc < KpadOut) {
                        __nv_bfloat16 h, l;
                        split_bf16(v, h, l);
                        outHi[(size_t)gr * KpadOut + gc] = h;
                        outLo[(size_t)gr * KpadOut + gc] = l;
                    }
                }
            }
        }
    }
}

// ---------------------------------------------------------------------------
// Conversions
// ---------------------------------------------------------------------------
__global__ void convA_kernel(const float* __restrict__ src,
                             __nv_bfloat16* __restrict__ hi, __nv_bfloat16* __restrict__ lo,
                             int K, int Kpad, long total)
{
    long i = (long)blockIdx.x * blockDim.x + threadIdx.x;
    if (i >= total) return;
    long r = i / Kpad;
    int  k = (int)(i - r * Kpad);
    float v = (k < K) ? src[r * K + k] : 0.f;
    __nv_bfloat16 h, l;
    split_bf16(v, h, l);
    hi[i] = h; lo[i] = l;
}

__global__ void convBT_kernel(const float* __restrict__ B,
                              __nv_bfloat16* __restrict__ bhi, __nv_bfloat16* __restrict__ blo,
                              int K, int N, int Kpad)
{
    __shared__ float sm[32][33];
    int k0 = blockIdx.x * 32, n0 = blockIdx.y * 32;
    int tx = threadIdx.x, ty = threadIdx.y;
    for (int i = ty; i < 32; i += 8) {
        int k = k0 + i, n = n0 + tx;
        sm[i][tx] = (k < K && n < N) ? B[(size_t)k * N + n] : 0.f;
    }
    __syncthreads();
    for (int i = ty; i < 32; i += 8) {
        int n = n0 + i, k = k0 + tx;
        if (n < N && k < Kpad) {
            __nv_bfloat16 h, l;
            split_bf16(sm[tx][i], h, l);
            bhi[(size_t)n * Kpad + k] = h;
            blo[(size_t)n * Kpad + k] = l;
        }
    }
}

// ---------------------------------------------------------------------------
// CSR build + CSR SpMM with fused activation
// ---------------------------------------------------------------------------
__global__ void csr_zero_kernel(int* cnt) {
    int i = blockIdx.x * blockDim.x + threadIdx.x;
    if (i <= NNODES) cnt[i] = 0;
}
__global__ void csr_count_kernel(const int* __restrict__ row, int* cnt, int E) {
    int e = blockIdx.x * blockDim.x + threadIdx.x;
    if (e < E) atomicAdd(&cnt[row[e] + 1], 1);
}
#define SCAN_PER 10
__global__ __launch_bounds__(1024) void csr_scan_kernel(const int* __restrict__ cnt,
                                                        int* rowptr, int* wp)
{
    __shared__ int sh[1024];
    int t = threadIdx.x;
    int base = t * SCAN_PER;
    int local[SCAN_PER];
    int s = 0;
#pragma unroll
    for (int i = 0; i < SCAN_PER; i++) {
        int idx = base + i;
        int v = (idx < NNODES) ? cnt[idx + 1] : 0;
        s += v;
        local[i] = s;
    }
    sh[t] = s;
    __syncthreads();
    for (int off = 1; off < 1024; off <<= 1) {
        int v = (t >= off) ? sh[t - off] : 0;
        __syncthreads();
        sh[t] += v;
        __syncthreads();
    }
    int prev = (t > 0) ? sh[t - 1] : 0;
    if (t == 0) rowptr[0] = 0;
#pragma unroll
    for (int i = 0; i < SCAN_PER; i++) {
        int idx = base + i;
        if (idx < NNODES) {
            rowptr[idx + 1] = prev + local[i];
            wp[idx] = (i == 0) ? prev : prev + local[i - 1];
        }
    }
}
__global__ void csr_scatter_kernel(const int* __restrict__ row, const int* __restrict__ col,
                                   const float* __restrict__ val, int* wp,
                                   int* scol, float* sval, int E)
{
    int e = blockIdx.x * blockDim.x + threadIdx.x;
    if (e >= E) return;
    int p = atomicAdd(&wp[row[e]], 1);
    scol[p] = col[e];
    sval[p] = val[e];
}

__global__ void spmm_csr_kernel(const float* __restrict__ H,
                                const int* __restrict__ rowptr,
                                const int* __restrict__ scol, const float* __restrict__ sval,
                                float* __restrict__ out, int D, int actmode)
{
    int r = blockIdx.x;
    int s = rowptr[r], e_end = rowptr[r + 1];
    int nt = blockDim.x;
    float acc[8];
    int nreg = (D + nt - 1) / nt;
#pragma unroll 8
    for (int i = 0; i < 8; i++) acc[i] = 0.f;
    for (int e = s; e < e_end; e++) {
        int c = scol[e];
        float v = sval[e];
        const float* hrow = H + (size_t)c * D;
#pragma unroll 8
        for (int i = 0; i < 8; i++) {
            if (i >= nreg) break;
            int d = threadIdx.x + i * nt;
            if (d < D) acc[i] = fmaf(v, hrow[d], acc[i]);
        }
    }
#pragma unroll 8
    for (int i = 0; i < 8; i++) {
        if (i >= nreg) break;
        int d = threadIdx.x + i * nt;
        if (d < D) {
            float o = acc[i];
            if (actmode == 0) o = o > 0.f ? o : expm1f(0.2f * o);
            else if (actmode == 1) o = o > 0.f ? o : expm1f(o);
            out[(size_t)r * D + d] = o;
        }
    }
}
static inline void spmm_csr(const float* H, float* out, int D, int actmode,
                            const int* rowptr, const int* scol, const float* sval)
{
    int threads = (D >= 256) ? 256 : ((D + 31) & ~31);
    spmm_csr_kernel<<<NNODES, threads>>>(H, rowptr, scol, sval, out, D, actmode);
}

// ---------------------------------------------------------------------------
// BatchNorm
// ---------------------------------------------------------------------------
__global__ void bn_stats_kernel(const float* __restrict__ h, int n, int d,
                                float* __restrict__ mean, float* __restrict__ rstd)
{
    __shared__ float ssum[8][32];
    __shared__ float ssq[8][32];
    int c = blockIdx.x * 32 + threadIdx.x;
    float s = 0.f, q = 0.f;
    if (c < d) {
        for (int r = threadIdx.y; r < n; r += 8) {
            float v = h[(size_t)r * d + c];
            s += v; q += v * v;
        }
    }
    ssum[threadIdx.y][threadIdx.x] = s;
    ssq[threadIdx.y][threadIdx.x] = q;
    __syncthreads();
    if (threadIdx.y == 0 && c < d) {
#pragma unroll
        for (int i = 1; i < 8; i++) { s += ssum[i][threadIdx.x]; q += ssq[i][threadIdx.x]; }
        float m = s / (float)n;
        float var = q / (float)n - m * m;
        if (var < 0.f) var = 0.f;
        mean[c] = m;
        rstd[c] = rsqrtf(var + 1e-5f);
    }
}
__global__ void bn_apply_kernel(const float* __restrict__ src, float* __restrict__ dst,
                                long total, int d, int Kpad,
                                const float* __restrict__ mean, const float* __restrict__ rstd,
                                __nv_bfloat16* __restrict__ outHi, __nv_bfloat16* __restrict__ outLo)
{
    long i = (long)blockIdx.x * blockDim.x + threadIdx.x;
    if (i >= total) return;
    long r = i / Kpad;
    int  c = (int)(i - r * Kpad);
    float v = 0.f;
    if (c < d) {
        v = (src[r * d + c] - mean[c]) * rstd[c];
        dst[r * d + c] = v;
    }
    if (outHi) {
        __nv_bfloat16 h, l;
        split_bf16(v, h, l);
        outHi[i] = h; outLo[i] = l;
    }
}
static inline void batchnorm(const float* src, float* dst, int n, int d,
                             float* mean, float* rstd,
                             __nv_bfloat16* outHi = nullptr, __nv_bfloat16* outLo = nullptr,
                             int Kpad = 0)
{
    dim3 bt(32, 8);
    bn_stats_kernel<<<(d + 31) / 32, bt>>>(src, n, d, mean, rstd);
    int kp = outHi ? Kpad : d;
    long total = (long)n * kp;
    bn_apply_kernel<<<(int)((total + 255) / 256), 256>>>(src, dst, total, d, kp, mean, rstd, outHi, outLo);
}

// ---------------------------------------------------------------------------
// Gate u, z_in, attention, softmax, q
// ---------------------------------------------------------------------------
__device__ __forceinline__ float coms_at(const float* t1, const float* t2,
                                         const float* t3, const float* t4,
                                         int n, int k)
{
    if (k < 500)  return t1[(size_t)n * 500 + k];
    if (k < 1000) return t2[(size_t)n * 500 + (k - 500)];
    if (k < 3000) return t3[(size_t)n * 2000 + (k - 1000)];
    return t4[(size_t)n * 64 + (k - 3000)];
}

__global__ void u_kernel(const float* __restrict__ t1, const float* __restrict__ t2,
                         const float* __restrict__ t3, const float* __restrict__ t4,
                         const float* __restrict__ W, const float* __restrict__ b,
                         float* __restrict__ u)
{
    int warp = (blockIdx.x * blockDim.x + threadIdx.x) >> 5;
    int lane = threadIdx.x & 31;
    if (warp >= NNODES) return;
    float acc[5] = {0.f, 0.f, 0.f, 0.f, 0.f};
    for (int k = lane; k < COMS_D; k += 32) {
        float v = coms_at(t1, t2, t3, t4, warp, k);
        const float* w = &W[(size_t)k * 5];
#pragma unroll
        for (int j = 0; j < 5; j++) acc[j] = fmaf(v, w[j], acc[j]);
    }
#pragma unroll
    for (int j = 0; j < 5; j++) {
        for (int off = 16; off > 0; off >>= 1)
            acc[j] += __shfl_down_sync(0xFFFFFFFF, acc[j], off);
    }
    if (lane == 0) {
        float l[5], m = -1e30f;
#pragma unroll
        for (int j = 0; j < 5; j++) { l[j] = tanhf(acc[j] + b[j]); m = fmaxf(m, l[j]); }
        float s = 0.f;
#pragma unroll
        for (int j = 0; j < 5; j++) { l[j] = expf(l[j] - m); s += l[j]; }
        float nrm = 0.f;
#pragma unroll
        for (int j = 0; j < 5; j++) { l[j] /= s; nrm += l[j] * l[j]; }
        nrm = fmaxf(sqrtf(nrm), 1e-12f);
#pragma unroll
        for (int j = 0; j < 5; j++) u[(size_t)warp * 5 + j] = l[j] / nrm;
    }
}

__global__ void zin_conv_kernel(const float* __restrict__ t1, const float* __restrict__ t2,
                                const float* __restrict__ t3, const float* __restrict__ t4,
                                const float* __restrict__ u,
                                __nv_bfloat16* __restrict__ hi, __nv_bfloat16* __restrict__ lo)
{
    long i = (long)blockIdx.x * blockDim.x + threadIdx.x;
    long total = (long)NNODES * 3072;
    if (i >= total) return;
    int n = (int)(i / 3072);
    int k = (int)(i % 3072);
    float v = 0.f;
    if (k < COMS_D) {
        int seg = (k < 500) ? 0 : (k < 1000) ? 1 : (k < 3000) ? 2 : 3;
        v = u[(size_t)n * 5 + seg] * coms_at(t1, t2, t3, t4, n, k);
    }
    __nv_bfloat16 h, l;
    split_bf16(v, h, l);
    hi[i] = h; lo[i] = l;
}

__global__ void att_scores_kernel(const float* __restrict__ z, const float* __restrict__ ztopo,
                                  const float* __restrict__ W1, const float* __restrict__ b1,
                                  const float* __restrict__ w2, float* __restrict__ scores)
{
    int gw = (blockIdx.x * blockDim.x + threadIdx.x) >> 5;
    int lane = threadIdx.x & 31;
    if (gw >= NNODES * 2) return;
    int n = gw >> 1;
    int br = gw & 1;
    const float* s = br ? &ztopo[(size_t)n * NZC] : &z[(size_t)n * NZC];
    float partial = 0.f;
    for (int j = lane; j < 128; j += 32) {
        float h = b1[j];
        for (int k = 0; k < NZC; k++) h = fmaf(s[k], W1[(size_t)k * 128 + j], h);
        partial = fmaf(tanhf(h), w2[j], partial);
    }
    for (int off = 16; off > 0; off >>= 1)
        partial += __shfl_down_sync(0xFFFFFFFF, partial, off);
    if (lane == 0) scores[(size_t)n * 2 + br] = partial;
}

__global__ void att_combine_kernel(const float* __restrict__ z, const float* __restrict__ ztopo,
                                   const float* __restrict__ scores, float* __restrict__ embp)
{
    long i = (long)blockIdx.x * blockDim.x + threadIdx.x;
    long total = (long)NNODES * NZC;
    if (i >= total) return;
    int n = (int)(i >> 6);
    float s0 = scores[(size_t)n * 2 + 0];
    float s1 = scores[(size_t)n * 2 + 1];
    float m = fmaxf(s0, s1);
    float e0 = expf(s0 - m), e1 = expf(s1 - m);
    float inv = 1.f / (e0 + e1);
    embp[i] = (e0 * inv) * z[i] + (e1 * inv) * ztopo[i];
}

__global__ void rowsoftmax64_kernel(const float* __restrict__ in, float* __restrict__ out)
{
    int n = blockIdx.x;
    int t = threadIdx.x;
    __shared__ float sh[64];
    float v = in[(size_t)n * 64 + t];
    sh[t] = v;
    __syncthreads();
    for (int s = 32; s > 0; s >>= 1) {
        if (t < s) sh[t] = fmaxf(sh[t], sh[t + s]);
        __syncthreads();
    }
    float m = sh[0];
    __syncthreads();
    float e = expf(v - m);
    sh[t] = e;
    __syncthreads();
    for (int s = 32; s > 0; s >>= 1) {
        if (t < s) sh[t] += sh[t + s];
        __syncthreads();
    }
    out[(size_t)n * 64 + t] = e / sh[0];
}

__global__ void q_kernel(const float* __restrict__ z, const float* __restrict__ cluster,
                         float* __restrict__ q)
{
    int n = blockIdx.x;
    int t = threadIdx.x;
    __shared__ float zs[64];
    __shared__ float red[64];
    zs[t] = z[(size_t)n * 64 + t];
    __syncthreads();
    float d2 = 0.f;
    const float* c = &cluster[(size_t)t * 64];
    for (int k = 0; k < 64; k++) {
        float diff = zs[k] - c[k];
        d2 = fmaf(diff, diff, d2);
    }
    float qv = 1.f / (1.f + d2);
    red[t] = qv;
    __syncthreads();
    for (int s = 32; s > 0; s >>= 1) {
        if (t < s) red[t] += red[t + s];
        __syncthreads();
    }
    q[(size_t)n * 64 + t] = qv / red[0];
}

// ---------------------------------------------------------------------------
// Host-side GEMM dispatch
// ---------------------------------------------------------------------------
static inline void gemm_pre(const __nv_bfloat16* aHi, const __nv_bfloat16* aLo,
                            const float* Bw, const float* bias, float* C,
                            __nv_bfloat16* outHi, __nv_bfloat16* outLo,
                            int M, int N, int K, int mode,
                            __nv_bfloat16* Whi, __nv_bfloat16* Wlo)
{
    int Kpad = (K + 31) & ~31;
    int KpadOut = (N + 31) & ~31;
    dim3 tg((Kpad + 31) / 32, (N + 31) / 32);
    convBT_kernel<<<tg, dim3(32, 8)>>>(Bw, Whi, Wlo, K, N, Kpad);
    cudaFuncSetAttribute(mma_gemm_kernel, cudaFuncAttributeMaxDynamicSharedMemorySize, GEMM_DSMEM);
    dim3 grid((N + 127) / 128, (M + 127) / 128);
    mma_gemm_kernel<<<grid, 128, GEMM_DSMEM>>>(aHi, aLo, Whi, Wlo, bias, C,
                                               outHi, outLo, KpadOut, M, N, Kpad, mode);
}

// ---------------------------------------------------------------------------
// Launch
// ---------------------------------------------------------------------------
extern "C" void kernel_launch(void* const* d_in, const int* in_sizes, int n_in,
                              void* d_out, int out_size)
{
    const float* x       = (const float*)d_in[0];
    const float* adj_val = (const float*)d_in[1];
    const float* enc1_w  = (const float*)d_in[2];
    const float* enc1_b  = (const float*)d_in[3];
    const float* enc2_w  = (const float*)d_in[4];
    const float* enc2_b  = (const float*)d_in[5];
    const float* enc3_w  = (const float*)d_in[6];
    const float* enc3_b  = (const float*)d_in[7];
    const float* zl_w    = (const float*)d_in[8];
    const float* zl_b    = (const float*)d_in[9];
    const float* dec1_w  = (const float*)d_in[10];
    const float* dec1_b  = (const float*)d_in[11];
    const float* dec2_w  = (const float*)d_in[12];
    const float* dec2_b  = (const float*)d_in[13];
    const float* dec3_w  = (const float*)d_in[14];
    const float* dec3_b  = (const float*)d_in[15];
    const float* xbar_w  = (const float*)d_in[16];
    const float* xbar_b  = (const float*)d_in[17];
    const float* t1_w    = (const float*)d_in[18];
    const float* t2_w    = (const float*)d_in[19];
    const float* t3_w    = (const float*)d_in[20];
    const float* t4_w    = (const float*)d_in[21];
    const float* agcn_w  = (const float*)d_in[22];
    const float* mlpl_w  = (const float*)d_in[23];
    const float* mlpl_b  = (const float*)d_in[24];
    const float* att_w1  = (const float*)d_in[25];
    const float* att_b1  = (const float*)d_in[26];
    const float* att_w2  = (const float*)d_in[27];
    const float* cluster = (const float*)d_in[28];
    const int*   adj_row = (const int*)d_in[29];
    const int*   adj_col = (const int*)d_in[30];
    const int E = in_sizes[1];

    float* out      = (float*)d_out;
    float* out_xbar = out;
    float* out_q    = out + (size_t)NNODES * NIN;
    float* out_pred = out_q + (size_t)NNODES * NZC;
    float* out_emb  = out_pred + (size_t)NNODES * NZC;

    float *z, *g, *traw, *t1, *t2, *t3, *t4, *u, *ztopo, *scores, *embp, *mean, *rstd;
    int *cnt, *rowptr, *wp, *scol;
    float *sval;
    __nv_bfloat16 *A0h, *A0l, *A1h, *A1l, *Wh, *Wl;
    cudaGetSymbolAddress((void**)&z,  g_zbuf);
    cudaGetSymbolAddress((void**)&g,  g_gbuf);
    cudaGetSymbolAddress((void**)&traw, g_traw);
    cudaGetSymbolAddress((void**)&t1, g_t1);
    cudaGetSymbolAddress((void**)&t2, g_t2);
    cudaGetSymbolAddress((void**)&t3, g_t3);
    cudaGetSymbolAddress((void**)&t4, g_t4);
    cudaGetSymbolAddress((void**)&u,  g_u);
    cudaGetSymbolAddress((void**)&ztopo, g_ztopo);
    cudaGetSymbolAddress((void**)&scores, g_scores);
    cudaGetSymbolAddress((void**)&embp, g_embp);
    cudaGetSymbolAddress((void**)&mean, g_mean);
    cudaGetSymbolAddress((void**)&rstd, g_rstd);
    cudaGetSymbolAddress((void**)&cnt, g_cnt);
    cudaGetSymbolAddress((void**)&rowptr, g_rowptr);
    cudaGetSymbolAddress((void**)&wp, g_wp);
    cudaGetSymbolAddress((void**)&scol, g_scol);
    cudaGetSymbolAddress((void**)&sval, g_sval);
    cudaGetSymbolAddress((void**)&A0h, g_A0hi);
    cudaGetSymbolAddress((void**)&A0l, g_A0lo);
    cudaGetSymbolAddress((void**)&A1h, g_A1hi);
    cudaGetSymbolAddress((void**)&A1l, g_A1lo);
    cudaGetSymbolAddress((void**)&Wh, g_Whi);
    cudaGetSymbolAddress((void**)&Wl, g_Wlo);

    // ---------------- CSR build ----------------
    csr_zero_kernel<<<(NNODES + 256) / 256, 256>>>(cnt);
    csr_count_kernel<<<(E + 255) / 256, 256>>>(adj_row, cnt, E);
    csr_scan_kernel<<<1, 1024>>>(cnt, rowptr, wp);
    csr_scatter_kernel<<<(E + 255) / 256, 256>>>(adj_row, adj_col, adj_val, wp, scol, sval, E);

    // ---------------- convert x once ----------------
    {
        int Kpad = 2016;
        long tA = (long)NNODES * Kpad;
        convA_kernel<<<(int)((tA + 255) / 256), 256>>>(x, A0h, A0l, NIN, Kpad, tA);
    }

    // ---------------- topo t1 GEMM ----------------
    gemm_pre(A0h, A0l, t1_w, nullptr, g, nullptr, nullptr, NNODES, 500, NIN, 0, Wh, Wl);

    // ---------------- AE chain ----------------
    gemm_pre(A0h, A0l, enc1_w, enc1_b, nullptr, A1h, A1l, NNODES, D1, NIN, 2, Wh, Wl);
    gemm_pre(A1h, A1l, enc2_w, enc2_b, nullptr, A0h, A0l, NNODES, D2, D1, 2, Wh, Wl);
    gemm_pre(A0h, A0l, enc3_w, enc3_b, nullptr, A1h, A1l, NNODES, D3, D2, 2, Wh, Wl);
    gemm_pre(A1h, A1l, zl_w, zl_b, z, A0h, A0l, NNODES, NZC, D3, 1, Wh, Wl);
    gemm_pre(A0h, A0l, dec1_w, dec1_b, nullptr, A1h, A1l, NNODES, 2000, NZC, 2, Wh, Wl);
    gemm_pre(A1h, A1l, dec2_w, dec2_b, nullptr, A0h, A0l, NNODES, 500, 2000, 2, Wh, Wl);
    gemm_pre(A0h, A0l, dec3_w, dec3_b, nullptr, A1h, A1l, NNODES, 500, 500, 2, Wh, Wl);
    gemm_pre(A1h, A1l, xbar_w, xbar_b, out_xbar, nullptr, nullptr, NNODES, NIN, 500, 1, Wh, Wl);

    // ---------------- topo GCN stack ----------------
    spmm_csr(g, traw, 500, 0, rowptr, scol, sval);
    batchnorm(traw, t1, NNODES, 500, mean, rstd, A0h, A0l, 512);
    gemm_pre(A0h, A0l, t2_w, nullptr, g, nullptr, nullptr, NNODES, 500, 500, 0, Wh, Wl);

    spmm_csr(g, traw, 500, 0, rowptr, scol, sval);
    batchnorm(traw, t2, NNODES, 500, mean, rstd, A0h, A0l, 512);
    gemm_pre(A0h, A0l, t3_w, nullptr, g, nullptr, nullptr, NNODES, 2000, 500, 0, Wh, Wl);

    spmm_csr(g, traw, 2000, 0, rowptr, scol, sval);
    batchnorm(traw, t3, NNODES, 2000, mean, rstd, A0h, A0l, 2016);
    gemm_pre(A0h, A0l, t4_w, nullptr, g, nullptr, nullptr, NNODES, NZC, 2000, 0, Wh, Wl);

    spmm_csr(g, traw, NZC, 0, rowptr, scol, sval);
    batchnorm(traw, t4, NNODES, NZC, mean, rstd);

    // ---------------- MLP gate u + z_in + agcn ----------------
    u_kernel<<<(NNODES * 32 + 255) / 256, 256>>>(t1, t2, t3, t4, mlpl_w, mlpl_b, u);
    {
        long total = (long)NNODES * 3072;
        zin_conv_kernel<<<(int)((total + 255) / 256), 256>>>(t1, t2, t3, t4, u, A0h, A0l);
    }
    gemm_pre(A0h, A0l, agcn_w, nullptr, g, nullptr, nullptr, NNODES, NZC, COMS_D, 0, Wh, Wl);
    spmm_csr(g, traw, NZC, 1, rowptr, scol, sval);
    batchnorm(traw, ztopo, NNODES, NZC, mean, rstd);

    // ---------------- attention fusion ----------------
    att_scores_kernel<<<(NNODES * 2 * 32 + 255) / 256, 256>>>(z, ztopo, att_w1, att_b1, att_w2, scores);
    {
        long total = (long)NNODES * NZC;
        att_combine_kernel<<<(int)((total + 255) / 256), 256>>>(z, ztopo, scores, embp);
    }
    batchnorm(embp, out_emb, NNODES, NZC, mean, rstd);
    rowsoftmax64_kernel<<<NNODES, 64>>>(out_emb, out_pred);

    // ---------------- Student-t q ----------------
    q_kernel<<<NNODES, 64>>>(z, cluster, out_q);
}

// round 10
// speedup vs baseline: 1.1292x; 1.1292x over previous
#include <cuda_runtime.h>
#include <cuda_bf16.h>
#include <math.h>
#include <stdint.h>

// ---------------------------------------------------------------------------
// Problem constants
// ---------------------------------------------------------------------------
#define NNODES 10000
#define NIN    2000
#define D1     500
#define D2     500
#define D3     2000
#define NZC    64
#define COMS_D 3064
#define EMAX   131072

// ---------------------------------------------------------------------------
// Scratch (device globals; no allocations allowed)
// ---------------------------------------------------------------------------
__device__ float g_zbuf [NNODES * NZC];
__device__ float g_gbuf [NNODES * 2000];
__device__ float g_traw [NNODES * 2000];
__device__ float g_t1[NNODES * 500];
__device__ float g_t2[NNODES * 500];
__device__ float g_t3[NNODES * 2000];
__device__ float g_t4[NNODES * NZC];
__device__ float g_u [NNODES * 5];
__device__ float g_ztopo[NNODES * NZC];
__device__ float g_embp[NNODES * NZC];
__device__ float g_mean[4096];
__device__ float g_rstd[4096];

// CSR build
__device__ int   g_cnt[NNODES + 1];
__device__ int   g_rowptr[NNODES + 1];
__device__ int   g_wp[NNODES];
__device__ int   g_scol[EMAX];
__device__ float g_sval[EMAX];

// bf16 split-precision ping-pong A buffers + weight buffers
__device__ __align__(256) __nv_bfloat16 g_A0hi[(size_t)NNODES * 3072];
__device__ __align__(256) __nv_bfloat16 g_A0lo[(size_t)NNODES * 3072];
__device__ __align__(256) __nv_bfloat16 g_A1hi[(size_t)NNODES * 3072];
__device__ __align__(256) __nv_bfloat16 g_A1lo[(size_t)NNODES * 3072];
__device__ __align__(256) __nv_bfloat16 g_Whi[2048 * 3072];
__device__ __align__(256) __nv_bfloat16 g_Wlo[2048 * 3072];

// ---------------------------------------------------------------------------
// PTX helpers (ldmatrix / mma.sync only)
// ---------------------------------------------------------------------------
__device__ __forceinline__ void ldsm4(uint32_t* r, uint32_t addr) {
    asm volatile("ldmatrix.sync.aligned.m8n8.x4.shared.b16 {%0,%1,%2,%3}, [%4];"
                 : "=r"(r[0]), "=r"(r[1]), "=r"(r[2]), "=r"(r[3]) : "r"(addr));
}
__device__ __forceinline__ uint32_t smem_u32(const void* p) {
    uint32_t a;
    asm("{ .reg .u64 t; cvta.to.shared.u64 t, %1; cvt.u32.u64 %0, t; }" : "=r"(a) : "l"(p));
    return a;
}
__device__ __forceinline__ void mma16816(float* c, const uint32_t* a, const uint32_t* b) {
    asm volatile(
        "mma.sync.aligned.m16n8k16.row.col.f32.bf16.bf16.f32 "
        "{%0,%1,%2,%3}, {%4,%5,%6,%7}, {%8,%9}, {%0,%1,%2,%3};"
        : "+f"(c[0]), "+f"(c[1]), "+f"(c[2]), "+f"(c[3])
        : "r"(a[0]), "r"(a[1]), "r"(a[2]), "r"(a[3]), "r"(b[0]), "r"(b[1]));
}
__device__ __forceinline__ void split_bf16(float v, __nv_bfloat16& h, __nv_bfloat16& l) {
    h = __float2bfloat16(v);
    l = __float2bfloat16(v - __bfloat162float(h));
}

// ---------------------------------------------------------------------------
// Split-bf16 mma.sync GEMM (exact R8 config: BM=128 BN=64 BK=32, 256 thr,
// warps 4m x 2n, 32x32 warp tile, double-buffered smem, one sync/chunk).
// C may be nullptr. mode: 0 none, 1 +bias, 2 +bias+elu
// ---------------------------------------------------------------------------
#define ROWB 80
#define A_BYTES (128 * ROWB)
#define B_BYTES (64 * ROWB)
#define STAGE_BYTES (2 * A_BYTES + 2 * B_BYTES)   // 30720
#define GEMM_DSMEM (2 * STAGE_BYTES)              // 61440

struct Prefetch { uint4 ahi[2], alo[2], bhi, blo; };

__device__ __forceinline__ void fetch_regs(
    Prefetch& p,
    const __nv_bfloat16* __restrict__ Ahi, const __nv_bfloat16* __restrict__ Alo,
    const __nv_bfloat16* __restrict__ Bhi, const __nv_bfloat16* __restrict__ Blo,
    int mBase, int M, int nBase, int N, int Kpad, int k0, int tid)
{
#pragma unroll
    for (int it = 0; it < 2; it++) {
        int t = tid + it * 256;
        int row = t >> 2, seg = t & 3;
        int gr = mBase + row;
        int sr = (gr < M) ? gr : 0;
        size_t off = (size_t)sr * Kpad + k0 + seg * 8;
        p.ahi[it] = *reinterpret_cast<const uint4*>(Ahi + off);
        p.alo[it] = *reinterpret_cast<const uint4*>(Alo + off);
    }
    {
        int row = tid >> 2, seg = tid & 3;
        int gn = nBase + row;
        int sn = (gn < N) ? gn : 0;
        size_t off = (size_t)sn * Kpad + k0 + seg * 8;
        p.bhi = *reinterpret_cast<const uint4*>(Bhi + off);
        p.blo = *reinterpret_cast<const uint4*>(Blo + off);
    }
}

__global__ __launch_bounds__(256, 2) void mma_gemm_kernel(
    const __nv_bfloat16* __restrict__ Ahi, const __nv_bfloat16* __restrict__ Alo,
    const __nv_bfloat16* __restrict__ Bhi, const __nv_bfloat16* __restrict__ Blo,
    const float* __restrict__ bias, float* __restrict__ C,
    __nv_bfloat16* __restrict__ outHi, __nv_bfloat16* __restrict__ outLo, int KpadOut,
    int M, int Ncol, int Kpad, int mode)
{
    extern __shared__ __align__(256) char smem[];
    uint32_t sb = smem_u32(smem);
    int tid = threadIdx.x;
    int wid = tid >> 5, lane = tid & 31;
    int wm = wid & 3, wn = wid >> 2;
    int mBase = blockIdx.y * 128;
    int nBase = blockIdx.x * 64;

    int arow0 = tid >> 2, aseg = tid & 3;
    uint32_t aOff0 = arow0 * ROWB + aseg * 16;
    uint32_t aOff1 = (arow0 + 64) * ROWB + aseg * 16;
    uint32_t bOff  = aOff0;

    float acc[2][4][4];
#pragma unroll
    for (int mt = 0; mt < 2; mt++)
#pragma unroll
        for (int nt = 0; nt < 4; nt++)
#pragma unroll
            for (int r = 0; r < 4; r++) acc[mt][nt][r] = 0.f;

    const int nc = Kpad >> 5;

    Prefetch pf;
    fetch_regs(pf, Ahi, Alo, Bhi, Blo, mBase, M, nBase, Ncol, Kpad, 0, tid);

    int lrow = (lane & 7) + ((lane >> 3) & 1) * 8;
    int lcol8 = (lane >> 4) * 8;

    for (int c = 0; c < nc; c++) {
        char* buf = smem + (c & 1) * STAGE_BYTES;
        uint32_t bufU = sb + (c & 1) * STAGE_BYTES;

        *reinterpret_cast<uint4*>(buf + aOff0)                        = pf.ahi[0];
        *reinterpret_cast<uint4*>(buf + aOff1)                        = pf.ahi[1];
        *reinterpret_cast<uint4*>(buf + A_BYTES + aOff0)              = pf.alo[0];
        *reinterpret_cast<uint4*>(buf + A_BYTES + aOff1)              = pf.alo[1];
        *reinterpret_cast<uint4*>(buf + 2 * A_BYTES + bOff)           = pf.bhi;
        *reinterpret_cast<uint4*>(buf + 2 * A_BYTES + B_BYTES + bOff) = pf.blo;
        __syncthreads();

        if (c + 1 < nc)
            fetch_regs(pf, Ahi, Alo, Bhi, Blo, mBase, M, nBase, Ncol, Kpad, (c + 1) * 32, tid);

        uint32_t aHiS = bufU;
        uint32_t aLoS = bufU + A_BYTES;
        uint32_t bHiS = bufU + 2 * A_BYTES;
        uint32_t bLoS = bHiS + B_BYTES;

#pragma unroll
        for (int ks = 0; ks < 2; ks++) {
            int kc = ks * 16 + lcol8;
            uint32_t ah[2][4], al[2][4];
#pragma unroll
            for (int mt = 0; mt < 2; mt++) {
                uint32_t o = (wm * 32 + mt * 16 + lrow) * ROWB + kc * 2;
                ldsm4(ah[mt], aHiS + o);
                ldsm4(al[mt], aLoS + o);
            }
            uint32_t bh[4][2], bl[4][2];
#pragma unroll
            for (int ntp = 0; ntp < 2; ntp++) {
                uint32_t o = (wn * 32 + ntp * 16 + lrow) * ROWB + kc * 2;
                uint32_t t[4];
                ldsm4(t, bHiS + o);
                bh[2 * ntp][0] = t[0]; bh[2 * ntp][1] = t[2];
                bh[2 * ntp + 1][0] = t[1]; bh[2 * ntp + 1][1] = t[3];
                ldsm4(t, bLoS + o);
                bl[2 * ntp][0] = t[0]; bl[2 * ntp][1] = t[2];
                bl[2 * ntp + 1][0] = t[1]; bl[2 * ntp + 1][1] = t[3];
            }
#pragma unroll
            for (int mt = 0; mt < 2; mt++)
#pragma unroll
                for (int nt = 0; nt < 4; nt++) {
                    mma16816(acc[mt][nt], ah[mt], bh[nt]);
                    mma16816(acc[mt][nt], ah[mt], bl[nt]);
                    mma16816(acc[mt][nt], al[mt], bh[nt]);
                }
        }
    }

    int qr = lane >> 2;
    int qc = (lane & 3) * 2;
#pragma unroll
    for (int mt = 0; mt < 2; mt++) {
#pragma unroll
        for (int nt = 0; nt < 4; nt++) {
#pragma unroll
            for (int half = 0; half < 2; half++) {
                int gr = mBase + wm * 32 + mt * 16 + qr + half * 8;
                if (gr >= M) continue;
#pragma unroll
                for (int e = 0; e < 2; e++) {
                    int gc = nBase + wn * 32 + nt * 8 + qc + e;
                    float v = acc[mt][nt][half * 2 + e];
                    if (gc < Ncol) {
                        if (mode >= 1) v += bias[gc];
                        if (mode == 2) v = v > 0.f ? v : expm1f(v);
                        if (C) C[(size_t)gr * Ncol + gc] = v;
                    } else {
                        v = 0.f;
                    }
                    if (outHi && gc < KpadOut) {
                        __nv_bfloat16 h, l;
                        split_bf16(v, h, l);
                        outHi[(size_t)gr * KpadOut + gc] = h;
                        outLo[(size_t)gr * KpadOut + gc] = l;
                    }
                }
            }
        }
    }
}

// ---------------------------------------------------------------------------
// Conversions
// ---------------------------------------------------------------------------
__global__ void convA_kernel(const float* __restrict__ src,
                             __nv_bfloat16* __restrict__ hi, __nv_bfloat16* __restrict__ lo,
                             int K, int Kpad, long total)
{
    long i = (long)blockIdx.x * blockDim.x + threadIdx.x;
    if (i >= total) return;
    long r = i / Kpad;
    int  k = (int)(i - r * Kpad);
    float v = (k < K) ? src[r * K + k] : 0.f;
    __nv_bfloat16 h, l;
    split_bf16(v, h, l);
    hi[i] = h; lo[i] = l;
}

__global__ void convBT_kernel(const float* __restrict__ B,
                              __nv_bfloat16* __restrict__ bhi, __nv_bfloat16* __restrict__ blo,
                              int K, int N, int Kpad)
{
    __shared__ float sm[32][33];
    int k0 = blockIdx.x * 32, n0 = blockIdx.y * 32;
    int tx = threadIdx.x, ty = threadIdx.y;
    for (int i = ty; i < 32; i += 8) {
        int k = k0 + i, n = n0 + tx;
        sm[i][tx] = (k < K && n < N) ? B[(size_t)k * N + n] : 0.f;
    }
    __syncthreads();
    for (int i = ty; i < 32; i += 8) {
        int n = n0 + i, k = k0 + tx;
        if (n < N && k < Kpad) {
            __nv_bfloat16 h, l;
            split_bf16(sm[tx][i], h, l);
            bhi[(size_t)n * Kpad + k] = h;
            blo[(size_t)n * Kpad + k] = l;
        }
    }
}

// ---------------------------------------------------------------------------
// CSR build + CSR SpMM with fused activation
// ---------------------------------------------------------------------------
__global__ void csr_zero_kernel(int* cnt) {
    int i = blockIdx.x * blockDim.x + threadIdx.x;
    if (i <= NNODES) cnt[i] = 0;
}
__global__ void csr_count_kernel(const int* __restrict__ row, int* cnt, int E) {
    int e = blockIdx.x * blockDim.x + threadIdx.x;
    if (e < E) atomicAdd(&cnt[row[e] + 1], 1);
}
#define SCAN_PER 10
__global__ __launch_bounds__(1024) void csr_scan_kernel(const int* __restrict__ cnt,
                                                        int* rowptr, int* wp)
{
    __shared__ int sh[1024];
    int t = threadIdx.x;
    int base = t * SCAN_PER;
    int local[SCAN_PER];
    int s = 0;
#pragma unroll
    for (int i = 0; i < SCAN_PER; i++) {
        int idx = base + i;
        int v = (idx < NNODES) ? cnt[idx + 1] : 0;
        s += v;
        local[i] = s;
    }
    sh[t] = s;
    __syncthreads();
    for (int off = 1; off < 1024; off <<= 1) {
        int v = (t >= off) ? sh[t - off] : 0;
        __syncthreads();
        sh[t] += v;
        __syncthreads();
    }
    int prev = (t > 0) ? sh[t - 1] : 0;
    if (t == 0) rowptr[0] = 0;
#pragma unroll
    for (int i = 0; i < SCAN_PER; i++) {
        int idx = base + i;
        if (idx < NNODES) {
            rowptr[idx + 1] = prev + local[i];
            wp[idx] = (i == 0) ? prev : prev + local[i - 1];
        }
    }
}
__global__ void csr_scatter_kernel(const int* __restrict__ row, const int* __restrict__ col,
                                   const float* __restrict__ val, int* wp,
                                   int* scol, float* sval, int E)
{
    int e = blockIdx.x * blockDim.x + threadIdx.x;
    if (e >= E) return;
    int p = atomicAdd(&wp[row[e]], 1);
    scol[p] = col[e];
    sval[p] = val[e];
}

__global__ void spmm_csr_kernel(const float* __restrict__ H,
                                const int* __restrict__ rowptr,
                                const int* __restrict__ scol, const float* __restrict__ sval,
                                float* __restrict__ out, int D, int actmode)
{
    int r = blockIdx.x;
    int s = rowptr[r], e_end = rowptr[r + 1];
    int nt = blockDim.x;
    float acc[8];
    int nreg = (D + nt - 1) / nt;
#pragma unroll 8
    for (int i = 0; i < 8; i++) acc[i] = 0.f;
    for (int e = s; e < e_end; e++) {
        int c = scol[e];
        float v = sval[e];
        const float* hrow = H + (size_t)c * D;
#pragma unroll 8
        for (int i = 0; i < 8; i++) {
            if (i >= nreg) break;
            int d = threadIdx.x + i * nt;
            if (d < D) acc[i] = fmaf(v, hrow[d], acc[i]);
        }
    }
#pragma unroll 8
    for (int i = 0; i < 8; i++) {
        if (i >= nreg) break;
        int d = threadIdx.x + i * nt;
        if (d < D) {
            float o = acc[i];
            if (actmode == 0) o = o > 0.f ? o : expm1f(0.2f * o);
            else if (actmode == 1) o = o > 0.f ? o : expm1f(o);
            out[(size_t)r * D + d] = o;
        }
    }
}
static inline void spmm_csr(const float* H, float* out, int D, int actmode,
                            const int* rowptr, const int* scol, const float* sval)
{
    int threads = (D >= 256) ? 256 : ((D + 31) & ~31);
    spmm_csr_kernel<<<NNODES, threads>>>(H, rowptr, scol, sval, out, D, actmode);
}

// ---------------------------------------------------------------------------
// BatchNorm
// ---------------------------------------------------------------------------
__global__ void bn_stats_kernel(const float* __restrict__ h, int n, int d,
                                float* __restrict__ mean, float* __restrict__ rstd)
{
    __shared__ float ssum[8][32];
    __shared__ float ssq[8][32];
    int c = blockIdx.x * 32 + threadIdx.x;
    float s = 0.f, q = 0.f;
    if (c < d) {
        for (int r = threadIdx.y; r < n; r += 8) {
            float v = h[(size_t)r * d + c];
            s += v; q += v * v;
        }
    }
    ssum[threadIdx.y][threadIdx.x] = s;
    ssq[threadIdx.y][threadIdx.x] = q;
    __syncthreads();
    if (threadIdx.y == 0 && c < d) {
#pragma unroll
        for (int i = 1; i < 8; i++) { s += ssum[i][threadIdx.x]; q += ssq[i][threadIdx.x]; }
        float m = s / (float)n;
        float var = q / (float)n - m * m;
        if (var < 0.f) var = 0.f;
        mean[c] = m;
        rstd[c] = rsqrtf(var + 1e-5f);
    }
}
__global__ void bn_apply_kernel(const float* __restrict__ src, float* __restrict__ dst,
                                long total, int d, int Kpad,
                                const float* __restrict__ mean, const float* __restrict__ rstd,
                                __nv_bfloat16* __restrict__ outHi, __nv_bfloat16* __restrict__ outLo)
{
    long i = (long)blockIdx.x * blockDim.x + threadIdx.x;
    if (i >= total) return;
    long r = i / Kpad;
    int  c = (int)(i - r * Kpad);
    float v = 0.f;
    if (c < d) {
        v = (src[r * d + c] - mean[c]) * rstd[c];
        dst[r * d + c] = v;
    }
    if (outHi) {
        __nv_bfloat16 h, l;
        split_bf16(v, h, l);
        outHi[i] = h; outLo[i] = l;
    }
}
static inline void batchnorm(const float* src, float* dst, int n, int d,
                             float* mean, float* rstd,
                             __nv_bfloat16* outHi = nullptr, __nv_bfloat16* outLo = nullptr,
                             int Kpad = 0)
{
    dim3 bt(32, 8);
    bn_stats_kernel<<<(d + 31) / 32, bt>>>(src, n, d, mean, rstd);
    int kp = outHi ? Kpad : d;
    long total = (long)n * kp;
    bn_apply_kernel<<<(int)((total + 255) / 256), 256>>>(src, dst, total, d, kp, mean, rstd, outHi, outLo);
}

// ---------------------------------------------------------------------------
// Gate u, z_in, fused attention, heads (softmax + q)
// ---------------------------------------------------------------------------
__device__ __forceinline__ float coms_at(const float* t1, const float* t2,
                                         const float* t3, const float* t4,
                                         int n, int k)
{
    if (k < 500)  return t1[(size_t)n * 500 + k];
    if (k < 1000) return t2[(size_t)n * 500 + (k - 500)];
    if (k < 3000) return t3[(size_t)n * 2000 + (k - 1000)];
    return t4[(size_t)n * 64 + (k - 3000)];
}

__global__ void u_kernel(const float* __restrict__ t1, const float* __restrict__ t2,
                         const float* __restrict__ t3, const float* __restrict__ t4,
                         const float* __restrict__ W, const float* __restrict__ b,
                         float* __restrict__ u)
{
    int warp = (blockIdx.x * blockDim.x + threadIdx.x) >> 5;
    int lane = threadIdx.x & 31;
    if (warp >= NNODES) return;
    float acc[5] = {0.f, 0.f, 0.f, 0.f, 0.f};
    for (int k = lane; k < COMS_D; k += 32) {
        float v = coms_at(t1, t2, t3, t4, warp, k);
        const float* w = &W[(size_t)k * 5];
#pragma unroll
        for (int j = 0; j < 5; j++) acc[j] = fmaf(v, w[j], acc[j]);
    }
#pragma unroll
    for (int j = 0; j < 5; j++) {
        for (int off = 16; off > 0; off >>= 1)
            acc[j] += __shfl_down_sync(0xFFFFFFFF, acc[j], off);
    }
    if (lane == 0) {
        float l[5], m = -1e30f;
#pragma unroll
        for (int j = 0; j < 5; j++) { l[j] = tanhf(acc[j] + b[j]); m = fmaxf(m, l[j]); }
        float s = 0.f;
#pragma unroll
        for (int j = 0; j < 5; j++) { l[j] = expf(l[j] - m); s += l[j]; }
        float nrm = 0.f;
#pragma unroll
        for (int j = 0; j < 5; j++) { l[j] /= s; nrm += l[j] * l[j]; }
        nrm = fmaxf(sqrtf(nrm), 1e-12f);
#pragma unroll
        for (int j = 0; j < 5; j++) u[(size_t)warp * 5 + j] = l[j] / nrm;
    }
}

__global__ void zin_conv_kernel(const float* __restrict__ t1, const float* __restrict__ t2,
                                const float* __restrict__ t3, const float* __restrict__ t4,
                                const float* __restrict__ u,
                                __nv_bfloat16* __restrict__ hi, __nv_bfloat16* __restrict__ lo)
{
    long i = (long)blockIdx.x * blockDim.x + threadIdx.x;
    long total = (long)NNODES * 3072;
    if (i >= total) return;
    int n = (int)(i / 3072);
    int k = (int)(i % 3072);
    float v = 0.f;
    if (k < COMS_D) {
        int seg = (k < 500) ? 0 : (k < 1000) ? 1 : (k < 3000) ? 2 : 3;
        v = u[(size_t)n * 5 + seg] * coms_at(t1, t2, t3, t4, n, k);
    }
    __nv_bfloat16 h, l;
    split_bf16(v, h, l);
    hi[i] = h; lo[i] = l;
}

// Fused attention: scores (both branches) + softmax-over-2 + combine.
// Block = 256 threads = 8 warps = 4 nodes x 2 branches; W1/b1/w2 in smem.
__global__ __launch_bounds__(256) void att_fused_kernel(
    const float* __restrict__ z, const float* __restrict__ ztopo,
    const float* __restrict__ W1, const float* __restrict__ b1,
    const float* __restrict__ w2, float* __restrict__ embp)
{
    __shared__ float sW1[64 * 128];
    __shared__ float sb1[128];
    __shared__ float sw2[128];
    __shared__ float sS[8][64];
    __shared__ float sc[8];
    int tid = threadIdx.x;
    for (int i = tid; i < 64 * 128; i += 256) sW1[i] = W1[i];
    if (tid < 128) { sb1[tid] = b1[tid]; sw2[tid] = w2[tid]; }

    int wid = tid >> 5, lane = tid & 31;
    int nodeBase = blockIdx.x * 4;
    int n = nodeBase + (wid >> 1);
    int br = wid & 1;
    bool valid = (n < NNODES);
    if (valid) {
        const float* s = br ? &ztopo[(size_t)n * 64] : &z[(size_t)n * 64];
        sS[wid][lane] = s[lane];
        sS[wid][lane + 32] = s[lane + 32];
    }
    __syncthreads();

    float partial = 0.f;
    if (valid) {
#pragma unroll
        for (int jj = 0; jj < 4; jj++) {
            int j = lane + jj * 32;
            float h = sb1[j];
#pragma unroll
            for (int k = 0; k < 64; k++)
                h = fmaf(sS[wid][k], sW1[k * 128 + j], h);
            partial = fmaf(tanhf(h), sw2[j], partial);
        }
    }
    for (int off = 16; off > 0; off >>= 1)
        partial += __shfl_down_sync(0xFFFFFFFF, partial, off);
    if (lane == 0) sc[wid] = partial;
    __syncthreads();

    int nl = tid >> 6;           // 0..3 local node
    int d  = tid & 63;
    int n2 = nodeBase + nl;
    if (n2 < NNODES) {
        float s0 = sc[nl * 2], s1 = sc[nl * 2 + 1];
        float m = fmaxf(s0, s1);
        float e0 = expf(s0 - m), e1 = expf(s1 - m);
        float inv = 1.f / (e0 + e1);
        embp[(size_t)n2 * 64 + d] = (e0 * inv) * z[(size_t)n2 * 64 + d]
                                  + (e1 * inv) * ztopo[(size_t)n2 * 64 + d];
    }
}

// Heads: pred = rowsoftmax(emb), q = student-t(z, cluster). One block/node.
__global__ void heads_kernel(const float* __restrict__ emb, const float* __restrict__ z,
                             const float* __restrict__ cluster,
                             float* __restrict__ pred, float* __restrict__ q)
{
    int n = blockIdx.x;
    int t = threadIdx.x;
    __shared__ float sh[64];
    __shared__ float zs[64];

    // softmax over emb row
    float v = emb[(size_t)n * 64 + t];
    sh[t] = v;
    __syncthreads();
    for (int s = 32; s > 0; s >>= 1) {
        if (t < s) sh[t] = fmaxf(sh[t], sh[t + s]);
        __syncthreads();
    }
    float m = sh[0];
    __syncthreads();
    float e = expf(v - m);
    sh[t] = e;
    __syncthreads();
    for (int s = 32; s > 0; s >>= 1) {
        if (t < s) sh[t] += sh[t + s];
        __syncthreads();
    }
    pred[(size_t)n * 64 + t] = e / sh[0];
    __syncthreads();

    // student-t q
    zs[t] = z[(size_t)n * 64 + t];
    __syncthreads();
    float d2 = 0.f;
    const float* c = &cluster[(size_t)t * 64];
    for (int k = 0; k < 64; k++) {
        float diff = zs[k] - c[k];
        d2 = fmaf(diff, diff, d2);
    }
    float qv = 1.f / (1.f + d2);
    sh[t] = qv;
    __syncthreads();
    for (int s = 32; s > 0; s >>= 1) {
        if (t < s) sh[t] += sh[t + s];
        __syncthreads();
    }
    q[(size_t)n * 64 + t] = qv / sh[0];
}

// ---------------------------------------------------------------------------
// Host-side GEMM dispatch
// ---------------------------------------------------------------------------
static inline void gemm_pre(const __nv_bfloat16* aHi, const __nv_bfloat16* aLo,
                            const float* Bw, const float* bias, float* C,
                            __nv_bfloat16* outHi, __nv_bfloat16* outLo,
                            int M, int N, int K, int mode,
                            __nv_bfloat16* Whi, __nv_bfloat16* Wlo)
{
    int Kpad = (K + 31) & ~31;
    int KpadOut = (N + 31) & ~31;
    dim3 tg((Kpad + 31) / 32, (N + 31) / 32);
    convBT_kernel<<<tg, dim3(32, 8)>>>(Bw, Whi, Wlo, K, N, Kpad);
    cudaFuncSetAttribute(mma_gemm_kernel, cudaFuncAttributeMaxDynamicSharedMemorySize, GEMM_DSMEM);
    dim3 grid((N + 63) / 64, (M + 127) / 128);
    mma_gemm_kernel<<<grid, 256, GEMM_DSMEM>>>(aHi, aLo, Whi, Wlo, bias, C,
                                               outHi, outLo, KpadOut, M, N, Kpad, mode);
}

// ---------------------------------------------------------------------------
// Launch
// ---------------------------------------------------------------------------
extern "C" void kernel_launch(void* const* d_in, const int* in_sizes, int n_in,
                              void* d_out, int out_size)
{
    const float* x       = (const float*)d_in[0];
    const float* adj_val = (const float*)d_in[1];
    const float* enc1_w  = (const float*)d_in[2];
    const float* enc1_b  = (const float*)d_in[3];
    const float* enc2_w  = (const float*)d_in[4];
    const float* enc2_b  = (const float*)d_in[5];
    const float* enc3_w  = (const float*)d_in[6];
    const float* enc3_b  = (const float*)d_in[7];
    const float* zl_w    = (const float*)d_in[8];
    const float* zl_b    = (const float*)d_in[9];
    const float* dec1_w  = (const float*)d_in[10];
    const float* dec1_b  = (const float*)d_in[11];
    const float* dec2_w  = (const float*)d_in[12];
    const float* dec2_b  = (const float*)d_in[13];
    const float* dec3_w  = (const float*)d_in[14];
    const float* dec3_b  = (const float*)d_in[15];
    const float* xbar_w  = (const float*)d_in[16];
    const float* xbar_b  = (const float*)d_in[17];
    const float* t1_w    = (const float*)d_in[18];
    const float* t2_w    = (const float*)d_in[19];
    const float* t3_w    = (const float*)d_in[20];
    const float* t4_w    = (const float*)d_in[21];
    const float* agcn_w  = (const float*)d_in[22];
    const float* mlpl_w  = (const float*)d_in[23];
    const float* mlpl_b  = (const float*)d_in[24];
    const float* att_w1  = (const float*)d_in[25];
    const float* att_b1  = (const float*)d_in[26];
    const float* att_w2  = (const float*)d_in[27];
    const float* cluster = (const float*)d_in[28];
    const int*   adj_row = (const int*)d_in[29];
    const int*   adj_col = (const int*)d_in[30];
    const int E = in_sizes[1];

    float* out      = (float*)d_out;
    float* out_xbar = out;
    float* out_q    = out + (size_t)NNODES * NIN;
    float* out_pred = out_q + (size_t)NNODES * NZC;
    float* out_emb  = out_pred + (size_t)NNODES * NZC;

    float *z, *g, *traw, *t1, *t2, *t3, *t4, *u, *ztopo, *embp, *mean, *rstd;
    int *cnt, *rowptr, *wp, *scol;
    float *sval;
    __nv_bfloat16 *A0h, *A0l, *A1h, *A1l, *Wh, *Wl;
    cudaGetSymbolAddress((void**)&z,  g_zbuf);
    cudaGetSymbolAddress((void**)&g,  g_gbuf);
    cudaGetSymbolAddress((void**)&traw, g_traw);
    cudaGetSymbolAddress((void**)&t1, g_t1);
    cudaGetSymbolAddress((void**)&t2, g_t2);
    cudaGetSymbolAddress((void**)&t3, g_t3);
    cudaGetSymbolAddress((void**)&t4, g_t4);
    cudaGetSymbolAddress((void**)&u,  g_u);
    cudaGetSymbolAddress((void**)&ztopo, g_ztopo);
    cudaGetSymbolAddress((void**)&embp, g_embp);
    cudaGetSymbolAddress((void**)&mean, g_mean);
    cudaGetSymbolAddress((void**)&rstd, g_rstd);
    cudaGetSymbolAddress((void**)&cnt, g_cnt);
    cudaGetSymbolAddress((void**)&rowptr, g_rowptr);
    cudaGetSymbolAddress((void**)&wp, g_wp);
    cudaGetSymbolAddress((void**)&scol, g_scol);
    cudaGetSymbolAddress((void**)&sval, g_sval);
    cudaGetSymbolAddress((void**)&A0h, g_A0hi);
    cudaGetSymbolAddress((void**)&A0l, g_A0lo);
    cudaGetSymbolAddress((void**)&A1h, g_A1hi);
    cudaGetSymbolAddress((void**)&A1l, g_A1lo);
    cudaGetSymbolAddress((void**)&Wh, g_Whi);
    cudaGetSymbolAddress((void**)&Wl, g_Wlo);

    // ---------------- CSR build ----------------
    csr_zero_kernel<<<(NNODES + 256) / 256, 256>>>(cnt);
    csr_count_kernel<<<(E + 255) / 256, 256>>>(adj_row, cnt, E);
    csr_scan_kernel<<<1, 1024>>>(cnt, rowptr, wp);
    csr_scatter_kernel<<<(E + 255) / 256, 256>>>(adj_row, adj_col, adj_val, wp, scol, sval, E);

    // ---------------- convert x once ----------------
    {
        int Kpad = 2016;
        long tA = (long)NNODES * Kpad;
        convA_kernel<<<(int)((tA + 255) / 256), 256>>>(x, A0h, A0l, NIN, Kpad, tA);
    }

    // ---------------- topo t1 GEMM ----------------
    gemm_pre(A0h, A0l, t1_w, nullptr, g, nullptr, nullptr, NNODES, 500, NIN, 0, Wh, Wl);

    // ---------------- AE chain ----------------
    gemm_pre(A0h, A0l, enc1_w, enc1_b, nullptr, A1h, A1l, NNODES, D1, NIN, 2, Wh, Wl);
    gemm_pre(A1h, A1l, enc2_w, enc2_b, nullptr, A0h, A0l, NNODES, D2, D1, 2, Wh, Wl);
    gemm_pre(A0h, A0l, enc3_w, enc3_b, nullptr, A1h, A1l, NNODES, D3, D2, 2, Wh, Wl);
    gemm_pre(A1h, A1l, zl_w, zl_b, z, A0h, A0l, NNODES, NZC, D3, 1, Wh, Wl);
    gemm_pre(A0h, A0l, dec1_w, dec1_b, nullptr, A1h, A1l, NNODES, 2000, NZC, 2, Wh, Wl);
    gemm_pre(A1h, A1l, dec2_w, dec2_b, nullptr, A0h, A0l, NNODES, 500, 2000, 2, Wh, Wl);
    gemm_pre(A0h, A0l, dec3_w, dec3_b, nullptr, A1h, A1l, NNODES, 500, 500, 2, Wh, Wl);
    gemm_pre(A1h, A1l, xbar_w, xbar_b, out_xbar, nullptr, nullptr, NNODES, NIN, 500, 1, Wh, Wl);

    // ---------------- topo GCN stack ----------------
    spmm_csr(g, traw, 500, 0, rowptr, scol, sval);
    batchnorm(traw, t1, NNODES, 500, mean, rstd, A0h, A0l, 512);
    gemm_pre(A0h, A0l, t2_w, nullptr, g, nullptr, nullptr, NNODES, 500, 500, 0, Wh, Wl);

    spmm_csr(g, traw, 500, 0, rowptr, scol, sval);
    batchnorm(traw, t2, NNODES, 500, mean, rstd, A0h, A0l, 512);
    gemm_pre(A0h, A0l, t3_w, nullptr, g, nullptr, nullptr, NNODES, 2000, 500, 0, Wh, Wl);

    spmm_csr(g, traw, 2000, 0, rowptr, scol, sval);
    batchnorm(traw, t3, NNODES, 2000, mean, rstd, A0h, A0l, 2016);
    gemm_pre(A0h, A0l, t4_w, nullptr, g, nullptr, nullptr, NNODES, NZC, 2000, 0, Wh, Wl);

    spmm_csr(g, traw, NZC, 0, rowptr, scol, sval);
    batchnorm(traw, t4, NNODES, NZC, mean, rstd);

    // ---------------- MLP gate u + z_in + agcn ----------------
    u_kernel<<<(NNODES * 32 + 255) / 256, 256>>>(t1, t2, t3, t4, mlpl_w, mlpl_b, u);
    {
        long total = (long)NNODES * 3072;
        zin_conv_kernel<<<(int)((total + 255) / 256), 256>>>(t1, t2, t3, t4, u, A0h, A0l);
    }
    gemm_pre(A0h, A0l, agcn_w, nullptr, g, nullptr, nullptr, NNODES, NZC, COMS_D, 0, Wh, Wl);
    spmm_csr(g, traw, NZC, 1, rowptr, scol, sval);
    batchnorm(traw, ztopo, NNODES, NZC, mean, rstd);

    // ---------------- fused attention ----------------
    att_fused_kernel<<<(NNODES + 3) / 4, 256>>>(z, ztopo, att_w1, att_b1, att_w2, embp);
    batchnorm(embp, out_emb, NNODES, NZC, mean, rstd);

    // ---------------- heads: pred softmax + Student-t q ----------------
    heads_kernel<<<NNODES, 64>>>(out_emb, z, cluster, out_pred, out_q);
}